// round 12
// baseline (speedup 1.0000x reference)
#include <cuda_runtime.h>
#include <cuda_bf16.h>
#include <cstdint>

#define B_ 8
#define S_ 2048
#define E_ 1024
#define H_ 64
#define M_ (B_*S_)
#define WP 72   // smem pitch (bf16)

// bf16 hi/lo projected tensors (q pre-scaled by 1/8)
__device__ __nv_bfloat16 g_qh[M_*H_], g_ql[M_*H_];
__device__ __nv_bfloat16 g_kh[M_*H_], g_kl[M_*H_];
__device__ __nv_bfloat16 g_vh[M_*H_], g_vl[M_*H_];
// pre-split, transposed weights: [3*64][1024] (k contiguous)
__device__ __nv_bfloat16 g_wh[192*E_], g_wl[192*E_];

__device__ __forceinline__ void mma_bf16(float d[4], const uint32_t a[4], const uint32_t b[2]) {
    asm volatile(
        "mma.sync.aligned.m16n8k16.row.col.f32.bf16.bf16.f32 "
        "{%0,%1,%2,%3}, {%4,%5,%6,%7}, {%8,%9}, {%0,%1,%2,%3};\n"
        : "+f"(d[0]), "+f"(d[1]), "+f"(d[2]), "+f"(d[3])
        : "r"(a[0]), "r"(a[1]), "r"(a[2]), "r"(a[3]), "r"(b[0]), "r"(b[1]));
}

__device__ __forceinline__ void ldsm4(uint32_t& d0, uint32_t& d1, uint32_t& d2, uint32_t& d3,
                                      const void* p) {
    uint32_t a = (uint32_t)__cvta_generic_to_shared(p);
    asm volatile("ldmatrix.sync.aligned.m8n8.x4.shared.b16 {%0,%1,%2,%3}, [%4];"
        : "=r"(d0), "=r"(d1), "=r"(d2), "=r"(d3) : "r"(a));
}
__device__ __forceinline__ void ldsm4t(uint32_t& d0, uint32_t& d1, uint32_t& d2, uint32_t& d3,
                                       const void* p) {
    uint32_t a = (uint32_t)__cvta_generic_to_shared(p);
    asm volatile("ldmatrix.sync.aligned.m8n8.x4.trans.shared.b16 {%0,%1,%2,%3}, [%4];"
        : "=r"(d0), "=r"(d1), "=r"(d2), "=r"(d3) : "r"(a));
}

__device__ __forceinline__ void split2(float a, float b, uint32_t& h, uint32_t& l) {
    __nv_bfloat162 hb = __floats2bfloat162_rn(a, b);
    h = *reinterpret_cast<uint32_t*>(&hb);
    __nv_bfloat162 lb = __floats2bfloat162_rn(a - __low2float(hb), b - __high2float(hb));
    l = *reinterpret_cast<uint32_t*>(&lb);
}

// exp(x) for x <= 0 on the FMA/ALU pipes (no MUFU). |err| ~ 1e-7 rel.
__device__ __forceinline__ float fast_exp(float x) {
    x = fmaxf(x, -87.0f);
    float y = fmaf(x, 1.4426950408889634f, 12582912.0f);   // low bits = round(x*log2e)
    float n = y - 12582912.0f;
    float f = fmaf(x, 1.4426950408889634f, -n);            // f in [-0.5, 0.5]
    float p =             1.5403530e-4f;                    // ln2^6/720
    p = fmaf(p, f, 1.3333558e-3f);                          // ln2^5/120
    p = fmaf(p, f, 9.6181291e-3f);                          // ln2^4/24
    p = fmaf(p, f, 5.5504109e-2f);                          // ln2^3/6
    p = fmaf(p, f, 2.4022651e-1f);                          // ln2^2/2
    p = fmaf(p, f, 6.9314718e-1f);                          // ln2
    p = fmaf(p, f, 1.0f);
    int sc = (__float_as_int(y) << 23) + 0x3F800000;        // 2^n
    return p * __int_as_float(sc);
}

// ---------------------------------------------------------------------------
// convert_w: coalesced smem transpose. grid (16, 3), 256 threads.
// ---------------------------------------------------------------------------
__global__ __launch_bounds__(256) void convert_w(
    const float* __restrict__ wq, const float* __restrict__ wk, const float* __restrict__ wv)
{
    __shared__ float T[64][65];
    const int mat = blockIdx.y;
    const float* w = (mat==0) ? wq : ((mat==1) ? wk : wv);
    const int k0 = blockIdx.x * 64;
    const int t = threadIdx.x;
    #pragma unroll
    for (int i = 0; i < 16; i++) {
        int f = t + 256 * i;           // 0..4095
        int k = f >> 6, h = f & 63;
        T[k][h] = w[(size_t)(k0 + k) * H_ + h];
    }
    __syncthreads();
    #pragma unroll
    for (int i = 0; i < 16; i++) {
        int f = t + 256 * i;
        int h = f >> 6, k = f & 63;    // lanes: consecutive k -> coalesced global writes
        float v = T[k][h];
        __nv_bfloat16 hi = __float2bfloat16(v);
        g_wh[(size_t)(mat*64 + h) * E_ + k0 + k] = hi;
        g_wl[(size_t)(mat*64 + h) * E_ + k0 + k] = __float2bfloat16(v - __bfloat162float(hi));
    }
}

// ---------------------------------------------------------------------------
// qkv: 256 threads, 64-row M tile, N=192 (warp: 16 rows x 96 cols), BK=64
// ---------------------------------------------------------------------------
__global__ __launch_bounds__(256) void qkv_mma(
    const float* __restrict__ x,
    const float* __restrict__ bq, const float* __restrict__ bk, const float* __restrict__ bv)
{
    extern __shared__ __align__(16) __nv_bfloat16 qsm[];
    __nv_bfloat16* Xh = qsm;              // [64][WP]
    __nv_bfloat16* Xl = qsm + 4608;
    __nv_bfloat16* Wh = qsm + 9216;       // [192][WP]
    __nv_bfloat16* Wl = qsm + 23040;

    const int t    = threadIdx.x;
    const int w    = t >> 5;
    const int lane = t & 31;
    const int rl   = lane >> 2;
    const int kq   = (lane & 3) * 2;
    const int msub = w & 3;
    const int nhalf= w >> 2;
    const int m0   = blockIdx.x * 64;
    const int r0   = msub * 16 + rl;
    const int ksrow = (lane & 7) + 8 * ((lane >> 4) & 1);
    const int ksk   = 8 * ((lane >> 3) & 1);

    float acc[12][4];
    #pragma unroll
    for (int j = 0; j < 12; j++)
        #pragma unroll
        for (int i = 0; i < 4; i++) acc[j][i] = 0.f;

    for (int k0 = 0; k0 < E_; k0 += 64) {
        __syncthreads();
        #pragma unroll
        for (int i = 0; i < 2; i++) {
            int f = t + 256 * i;               // 0..511
            int r = f >> 3, c8 = (f & 7) * 8;
            const float* xp = x + (size_t)(m0 + r) * E_ + k0 + c8;
            float4 a = *(const float4*)xp;
            float4 b = *(const float4*)(xp + 4);
            uint4 hi, lo;
            split2(a.x, a.y, hi.x, lo.x);
            split2(a.z, a.w, hi.y, lo.y);
            split2(b.x, b.y, hi.z, lo.z);
            split2(b.z, b.w, hi.w, lo.w);
            *(uint4*)&Xh[r*WP + c8] = hi;
            *(uint4*)&Xl[r*WP + c8] = lo;
        }
        #pragma unroll
        for (int i = 0; i < 6; i++) {
            int f = t + 256 * i;               // 0..1535
            int r = f >> 3, c8 = (f & 7) * 8;
            *(uint4*)&Wh[r*WP + c8] = *(const uint4*)&g_wh[(size_t)r * E_ + k0 + c8];
            *(uint4*)&Wl[r*WP + c8] = *(const uint4*)&g_wl[(size_t)r * E_ + k0 + c8];
        }
        __syncthreads();

        #pragma unroll
        for (int kk = 0; kk < 4; kk++) {
            int kb = kk * 16 + kq;
            uint32_t Ah[4], Al[4];
            Ah[0] = *(const uint32_t*)&Xh[(r0  )*WP + kb  ];
            Ah[1] = *(const uint32_t*)&Xh[(r0+8)*WP + kb  ];
            Ah[2] = *(const uint32_t*)&Xh[(r0  )*WP + kb+8];
            Ah[3] = *(const uint32_t*)&Xh[(r0+8)*WP + kb+8];
            Al[0] = *(const uint32_t*)&Xl[(r0  )*WP + kb  ];
            Al[1] = *(const uint32_t*)&Xl[(r0+8)*WP + kb  ];
            Al[2] = *(const uint32_t*)&Xl[(r0  )*WP + kb+8];
            Al[3] = *(const uint32_t*)&Xl[(r0+8)*WP + kb+8];
            uint32_t Bh[12][2], Bl[12][2];
            #pragma unroll
            for (int p = 0; p < 6; p++) {
                int rowbase = nhalf*96 + 16*p + ksrow;
                ldsm4(Bh[2*p][0], Bh[2*p][1], Bh[2*p+1][0], Bh[2*p+1][1],
                      &Wh[rowbase*WP + kk*16 + ksk]);
                ldsm4(Bl[2*p][0], Bl[2*p][1], Bl[2*p+1][0], Bl[2*p+1][1],
                      &Wl[rowbase*WP + kk*16 + ksk]);
            }
            #pragma unroll
            for (int j = 0; j < 12; j++) mma_bf16(acc[j], Ah, Bh[j]);
            #pragma unroll
            for (int j = 0; j < 12; j++) mma_bf16(acc[j], Ah, Bl[j]);
            #pragma unroll
            for (int j = 0; j < 12; j++) mma_bf16(acc[j], Al, Bh[j]);
        }
    }

    const float* bs[3] = {bq, bk, bv};
    __nv_bfloat16* oh[3] = {g_qh, g_kh, g_vh};
    __nv_bfloat16* ol[3] = {g_ql, g_kl, g_vl};
    #pragma unroll
    for (int j = 0; j < 12; j++) {
        int gn = nhalf*12 + j;
        int ct = gn * 8 + kq;
        int mat = ct >> 6, cl = ct & 63;
        float sc = (mat == 0) ? 0.125f : 1.0f;
        float b0 = bs[mat][cl], b1 = bs[mat][cl+1];
        size_t row = (size_t)(m0 + r0);
        uint32_t h0, l0, h1, l1;
        split2((acc[j][0] + b0) * sc, (acc[j][1] + b1) * sc, h0, l0);
        split2((acc[j][2] + b0) * sc, (acc[j][3] + b1) * sc, h1, l1);
        *(uint32_t*)&oh[mat][ row      * H_ + cl] = h0;
        *(uint32_t*)&ol[mat][ row      * H_ + cl] = l0;
        *(uint32_t*)&oh[mat][(row + 8) * H_ + cl] = h1;
        *(uint32_t*)&ol[mat][(row + 8) * H_ + cl] = l1;
    }
}

// ---------------------------------------------------------------------------
// fa: 256 threads = 2 warp-groups; group g handles kt = g, g+2, ...
// ---------------------------------------------------------------------------
__global__ __launch_bounds__(256) void fa_mma(float* __restrict__ Y)
{
    extern __shared__ __align__(16) __nv_bfloat16 fsm[];
    __nv_bfloat16* Qh = fsm;                       // [64][WP]
    __nv_bfloat16* Ql = fsm + 4608;

    const int b    = blockIdx.y;
    const int qt   = 31 - blockIdx.x;              // heavy tiles first
    const int t    = threadIdx.x;
    const int w    = t >> 5;
    const int lane = t & 31;
    const int rl   = lane >> 2;
    const int cq   = (lane & 3) * 2;
    const int g    = w >> 2;                       // warp group 0/1
    const int qrow = (w & 3) * 16 + rl;
    const int gt   = t & 127;
    const int ksrow = (lane & 7) + 8 * ((lane >> 4) & 1);
    const int ksk   = 8 * ((lane >> 3) & 1);
    const int vsrow = (lane & 7) + 8 * ((lane >> 3) & 1);
    const int vsh   = 8 * ((lane >> 4) & 1);

    __nv_bfloat16* Kh = fsm + 9216 + g * 18432;
    __nv_bfloat16* Kl = Kh + 4608;
    __nv_bfloat16* Vh = Kh + 9216;
    __nv_bfloat16* Vl = Kh + 13824;

    const size_t qbase  = (size_t)(b * S_ + qt * 64);
    const size_t kvbase = (size_t)b * S_;

    #pragma unroll
    for (int i = 0; i < 2; i++) {
        int f = t + 256 * i;                 // 0..511
        int r = f >> 3, c8 = (f & 7) * 8;
        *(uint4*)&Qh[r*WP + c8] = *(const uint4*)&g_qh[(qbase + r) * H_ + c8];
        *(uint4*)&Ql[r*WP + c8] = *(const uint4*)&g_ql[(qbase + r) * H_ + c8];
    }
    __syncthreads();

    uint32_t QAh[4][4], QAl[4][4];
    #pragma unroll
    for (int kk = 0; kk < 4; kk++) {
        int kb = kk * 16 + cq;
        QAh[kk][0] = *(const uint32_t*)&Qh[(qrow  )*WP + kb  ];
        QAh[kk][1] = *(const uint32_t*)&Qh[(qrow+8)*WP + kb  ];
        QAh[kk][2] = *(const uint32_t*)&Qh[(qrow  )*WP + kb+8];
        QAh[kk][3] = *(const uint32_t*)&Qh[(qrow+8)*WP + kb+8];
        QAl[kk][0] = *(const uint32_t*)&Ql[(qrow  )*WP + kb  ];
        QAl[kk][1] = *(const uint32_t*)&Ql[(qrow+8)*WP + kb  ];
        QAl[kk][2] = *(const uint32_t*)&Ql[(qrow  )*WP + kb+8];
        QAl[kk][3] = *(const uint32_t*)&Ql[(qrow+8)*WP + kb+8];
    }

    float o[8][4];
    #pragma unroll
    for (int j = 0; j < 8; j++)
        #pragma unroll
        for (int i = 0; i < 4; i++) o[j][i] = 0.f;
    float mrow[2] = {-1e30f, -1e30f};
    float lrow[2] = {0.f, 0.f};

    for (int kt = g; kt <= qt; kt += 2) {
        asm volatile("bar.sync %0, 128;" :: "r"(1 + g) : "memory");
        #pragma unroll
        for (int i = 0; i < 4; i++) {
            int f = gt + 128 * i;            // 0..511
            int r = f >> 3, c8 = (f & 7) * 8;
            size_t gi = (kvbase + kt * 64 + r) * H_ + c8;
            *(uint4*)&Kh[r*WP + c8] = *(const uint4*)&g_kh[gi];
            *(uint4*)&Kl[r*WP + c8] = *(const uint4*)&g_kl[gi];
            *(uint4*)&Vh[r*WP + c8] = *(const uint4*)&g_vh[gi];
            *(uint4*)&Vl[r*WP + c8] = *(const uint4*)&g_vl[gi];
        }
        asm volatile("bar.sync %0, 128;" :: "r"(1 + g) : "memory");

        // ---- S = Qs @ K^T ----
        float s[8][4];
        #pragma unroll
        for (int j = 0; j < 8; j++)
            #pragma unroll
            for (int i = 0; i < 4; i++) s[j][i] = 0.f;

        #pragma unroll
        for (int kk = 0; kk < 4; kk++) {
            uint32_t Bh[8][2], Bl[8][2];
            #pragma unroll
            for (int p = 0; p < 4; p++) {
                ldsm4(Bh[2*p][0], Bh[2*p][1], Bh[2*p+1][0], Bh[2*p+1][1],
                      &Kh[(16*p + ksrow)*WP + kk*16 + ksk]);
                ldsm4(Bl[2*p][0], Bl[2*p][1], Bl[2*p+1][0], Bl[2*p+1][1],
                      &Kl[(16*p + ksrow)*WP + kk*16 + ksk]);
            }
            #pragma unroll
            for (int j = 0; j < 8; j++) mma_bf16(s[j], QAh[kk], Bh[j]);
            #pragma unroll
            for (int j = 0; j < 8; j++) mma_bf16(s[j], QAh[kk], Bl[j]);
            #pragma unroll
            for (int j = 0; j < 8; j++) mma_bf16(s[j], QAl[kk], Bh[j]);
        }

        if (kt == qt) {
            #pragma unroll
            for (int j = 0; j < 8; j++) {
                int c0 = j * 8 + cq;
                if (c0     > qrow)     s[j][0] = -1e30f;
                if (c0 + 1 > qrow)     s[j][1] = -1e30f;
                if (c0     > qrow + 8) s[j][2] = -1e30f;
                if (c0 + 1 > qrow + 8) s[j][3] = -1e30f;
            }
        }

        // ---- online softmax (fast_exp on FMA pipe) ----
        float mx0 = -1e30f, mx1 = -1e30f;
        #pragma unroll
        for (int j = 0; j < 8; j++) {
            mx0 = fmaxf(mx0, fmaxf(s[j][0], s[j][1]));
            mx1 = fmaxf(mx1, fmaxf(s[j][2], s[j][3]));
        }
        mx0 = fmaxf(mx0, __shfl_xor_sync(0xffffffffu, mx0, 1));
        mx0 = fmaxf(mx0, __shfl_xor_sync(0xffffffffu, mx0, 2));
        mx1 = fmaxf(mx1, __shfl_xor_sync(0xffffffffu, mx1, 1));
        mx1 = fmaxf(mx1, __shfl_xor_sync(0xffffffffu, mx1, 2));

        float mn0 = fmaxf(mrow[0], mx0), mn1 = fmaxf(mrow[1], mx1);
        float corr0 = fast_exp(mrow[0] - mn0), corr1 = fast_exp(mrow[1] - mn1);
        mrow[0] = mn0; mrow[1] = mn1;

        float sum0 = 0.f, sum1 = 0.f;
        #pragma unroll
        for (int j = 0; j < 8; j++) {
            s[j][0] = fast_exp(s[j][0] - mn0);
            s[j][1] = fast_exp(s[j][1] - mn0);
            s[j][2] = fast_exp(s[j][2] - mn1);
            s[j][3] = fast_exp(s[j][3] - mn1);
            sum0 += s[j][0] + s[j][1];
            sum1 += s[j][2] + s[j][3];
        }
        sum0 += __shfl_xor_sync(0xffffffffu, sum0, 1);
        sum0 += __shfl_xor_sync(0xffffffffu, sum0, 2);
        sum1 += __shfl_xor_sync(0xffffffffu, sum1, 1);
        sum1 += __shfl_xor_sync(0xffffffffu, sum1, 2);
        lrow[0] = lrow[0] * corr0 + sum0;
        lrow[1] = lrow[1] * corr1 + sum1;

        #pragma unroll
        for (int j = 0; j < 8; j++) {
            o[j][0] *= corr0; o[j][1] *= corr0;
            o[j][2] *= corr1; o[j][3] *= corr1;
        }

        // ---- P frags (hi/lo) in regs ----
        uint32_t Ph[4][4], Pl[4][4];
        #pragma unroll
        for (int kk = 0; kk < 4; kk++) {
            #pragma unroll
            for (int half = 0; half < 2; half++) {
                int jj = 2*kk + half;
                split2(s[jj][0], s[jj][1], Ph[kk][half*2+0], Pl[kk][half*2+0]);
                split2(s[jj][2], s[jj][3], Ph[kk][half*2+1], Pl[kk][half*2+1]);
            }
        }

        // ---- O += P @ V ----
        #pragma unroll
        for (int kk = 0; kk < 4; kk++) {
            uint32_t Bh[8][2], Bl[8][2];
            #pragma unroll
            for (int p = 0; p < 4; p++) {
                ldsm4t(Bh[2*p][0], Bh[2*p][1], Bh[2*p+1][0], Bh[2*p+1][1],
                       &Vh[(kk*16 + vsrow)*WP + 16*p + vsh]);
                ldsm4t(Bl[2*p][0], Bl[2*p][1], Bl[2*p+1][0], Bl[2*p+1][1],
                       &Vl[(kk*16 + vsrow)*WP + 16*p + vsh]);
            }
            #pragma unroll
            for (int jh = 0; jh < 8; jh++) mma_bf16(o[jh], Ph[kk], Bh[jh]);
            #pragma unroll
            for (int jh = 0; jh < 8; jh++) mma_bf16(o[jh], Ph[kk], Bl[jh]);
            #pragma unroll
            for (int jh = 0; jh < 8; jh++) mma_bf16(o[jh], Pl[kk], Bh[jh]);
        }
    }

    // ---- merge the two groups' partial states ----
    float* mbuf = (float*)((char*)fsm + 55296);   // inside group-1 KV region; stride 37
    if (g == 1) {
        float* p = mbuf + gt * 37;
        p[0] = mrow[0]; p[1] = mrow[1]; p[2] = lrow[0]; p[3] = lrow[1];
        #pragma unroll
        for (int j = 0; j < 8; j++)
            #pragma unroll
            for (int i = 0; i < 4; i++) p[4 + j*4 + i] = o[j][i];
    }
    __syncthreads();
    if (g == 0) {
        const float* p = mbuf + gt * 37;
        float m1a = p[0], m1b = p[1], l1a = p[2], l1b = p[3];
        float mA = fmaxf(mrow[0], m1a), mB = fmaxf(mrow[1], m1b);
        float w0a = fast_exp(mrow[0] - mA), w1a = fast_exp(m1a - mA);
        float w0b = fast_exp(mrow[1] - mB), w1b = fast_exp(m1b - mB);
        float invA = 1.0f / (lrow[0] * w0a + l1a * w1a);
        float invB = 1.0f / (lrow[1] * w0b + l1b * w1b);
        float* Yb = Y + qbase * H_;
        #pragma unroll
        for (int j = 0; j < 8; j++) {
            int col = j * 8 + cq;
            float oa0 = (o[j][0] * w0a + p[4 + j*4 + 0] * w1a) * invA;
            float oa1 = (o[j][1] * w0a + p[4 + j*4 + 1] * w1a) * invA;
            float ob0 = (o[j][2] * w0b + p[4 + j*4 + 2] * w1b) * invB;
            float ob1 = (o[j][3] * w0b + p[4 + j*4 + 3] * w1b) * invB;
            *(float2*)(Yb + (size_t)(qrow    ) * H_ + col) = make_float2(oa0, oa1);
            *(float2*)(Yb + (size_t)(qrow + 8) * H_ + col) = make_float2(ob0, ob1);
        }
    }
}

// ---------------------------------------------------------------------------
extern "C" void kernel_launch(void* const* d_in, const int* in_sizes, int n_in,
                              void* d_out, int out_size)
{
    const float* x  = (const float*)d_in[0];
    const float* wq = (const float*)d_in[1];
    const float* bq = (const float*)d_in[2];
    const float* wk = (const float*)d_in[3];
    const float* bk = (const float*)d_in[4];
    const float* wv = (const float*)d_in[5];
    const float* bv = (const float*)d_in[6];
    float* y = (float*)d_out;

    convert_w<<<dim3(16, 3), 256>>>(wq, wk, wv);

    const int qsh = (4608*2 + 13824*2) * (int)sizeof(__nv_bfloat16);  // 73728
    cudaFuncSetAttribute(qkv_mma, cudaFuncAttributeMaxDynamicSharedMemorySize, qsh);
    qkv_mma<<<M_/64, 256, qsh>>>(x, bq, bk, bv);

    const int fsh = (9216 + 2*18432) * (int)sizeof(__nv_bfloat16);    // 92160
    cudaFuncSetAttribute(fa_mma, cudaFuncAttributeMaxDynamicSharedMemorySize, fsh);
    fa_mma<<<dim3(32, B_), 256, fsh>>>(y);
}

// round 13
// speedup vs baseline: 1.1839x; 1.1839x over previous
#include <cuda_runtime.h>
#include <cuda_bf16.h>
#include <cstdint>

#define B_ 8
#define S_ 2048
#define E_ 1024
#define H_ 64
#define M_ (B_*S_)
#define WP 72   // smem pitch (bf16)

// bf16 hi/lo projected tensors (q pre-scaled by 1/8)
__device__ __nv_bfloat16 g_qh[M_*H_], g_ql[M_*H_];
__device__ __nv_bfloat16 g_kh[M_*H_], g_kl[M_*H_];
__device__ __nv_bfloat16 g_vh[M_*H_], g_vl[M_*H_];
// pre-split, transposed weights: [3*64][1024] (k contiguous)
__device__ __nv_bfloat16 g_wh[192*E_], g_wl[192*E_];

__device__ __forceinline__ void mma_bf16(float d[4], const uint32_t a[4], const uint32_t b[2]) {
    asm volatile(
        "mma.sync.aligned.m16n8k16.row.col.f32.bf16.bf16.f32 "
        "{%0,%1,%2,%3}, {%4,%5,%6,%7}, {%8,%9}, {%0,%1,%2,%3};\n"
        : "+f"(d[0]), "+f"(d[1]), "+f"(d[2]), "+f"(d[3])
        : "r"(a[0]), "r"(a[1]), "r"(a[2]), "r"(a[3]), "r"(b[0]), "r"(b[1]));
}

__device__ __forceinline__ void ldsm4(uint32_t& d0, uint32_t& d1, uint32_t& d2, uint32_t& d3,
                                      const void* p) {
    uint32_t a = (uint32_t)__cvta_generic_to_shared(p);
    asm volatile("ldmatrix.sync.aligned.m8n8.x4.shared.b16 {%0,%1,%2,%3}, [%4];"
        : "=r"(d0), "=r"(d1), "=r"(d2), "=r"(d3) : "r"(a));
}
__device__ __forceinline__ void ldsm4t(uint32_t& d0, uint32_t& d1, uint32_t& d2, uint32_t& d3,
                                       const void* p) {
    uint32_t a = (uint32_t)__cvta_generic_to_shared(p);
    asm volatile("ldmatrix.sync.aligned.m8n8.x4.trans.shared.b16 {%0,%1,%2,%3}, [%4];"
        : "=r"(d0), "=r"(d1), "=r"(d2), "=r"(d3) : "r"(a));
}

__device__ __forceinline__ void split2(float a, float b, uint32_t& h, uint32_t& l) {
    __nv_bfloat162 hb = __floats2bfloat162_rn(a, b);
    h = *reinterpret_cast<uint32_t*>(&hb);
    __nv_bfloat162 lb = __floats2bfloat162_rn(a - __low2float(hb), b - __high2float(hb));
    l = *reinterpret_cast<uint32_t*>(&lb);
}

// ---------------------------------------------------------------------------
// convert_w: coalesced smem transpose. grid (16, 3), 256 threads.
// ---------------------------------------------------------------------------
__global__ __launch_bounds__(256) void convert_w(
    const float* __restrict__ wq, const float* __restrict__ wk, const float* __restrict__ wv)
{
    __shared__ float T[64][65];
    const int mat = blockIdx.y;
    const float* w = (mat==0) ? wq : ((mat==1) ? wk : wv);
    const int k0 = blockIdx.x * 64;
    const int t = threadIdx.x;
    #pragma unroll
    for (int i = 0; i < 16; i++) {
        int f = t + 256 * i;           // 0..4095
        int k = f >> 6, h = f & 63;
        T[k][h] = w[(size_t)(k0 + k) * H_ + h];
    }
    __syncthreads();
    #pragma unroll
    for (int i = 0; i < 16; i++) {
        int f = t + 256 * i;
        int h = f >> 6, k = f & 63;    // lanes: consecutive k -> coalesced global writes
        float v = T[k][h];
        __nv_bfloat16 hi = __float2bfloat16(v);
        g_wh[(size_t)(mat*64 + h) * E_ + k0 + k] = hi;
        g_wl[(size_t)(mat*64 + h) * E_ + k0 + k] = __float2bfloat16(v - __bfloat162float(hi));
    }
}

// ---------------------------------------------------------------------------
// qkv: 256 threads, 64-row M tile, N=192 (warp: 16 rows x 96 cols), BK=64
// ---------------------------------------------------------------------------
__global__ __launch_bounds__(256) void qkv_mma(
    const float* __restrict__ x,
    const float* __restrict__ bq, const float* __restrict__ bk, const float* __restrict__ bv)
{
    extern __shared__ __align__(16) __nv_bfloat16 qsm[];
    __nv_bfloat16* Xh = qsm;              // [64][WP]
    __nv_bfloat16* Xl = qsm + 4608;
    __nv_bfloat16* Wh = qsm + 9216;       // [192][WP]
    __nv_bfloat16* Wl = qsm + 23040;

    const int t    = threadIdx.x;
    const int w    = t >> 5;
    const int lane = t & 31;
    const int rl   = lane >> 2;
    const int kq   = (lane & 3) * 2;
    const int msub = w & 3;
    const int nhalf= w >> 2;
    const int m0   = blockIdx.x * 64;
    const int r0   = msub * 16 + rl;
    const int ksrow = (lane & 7) + 8 * ((lane >> 4) & 1);
    const int ksk   = 8 * ((lane >> 3) & 1);

    float acc[12][4];
    #pragma unroll
    for (int j = 0; j < 12; j++)
        #pragma unroll
        for (int i = 0; i < 4; i++) acc[j][i] = 0.f;

    for (int k0 = 0; k0 < E_; k0 += 64) {
        __syncthreads();
        #pragma unroll
        for (int i = 0; i < 2; i++) {
            int f = t + 256 * i;               // 0..511
            int r = f >> 3, c8 = (f & 7) * 8;
            const float* xp = x + (size_t)(m0 + r) * E_ + k0 + c8;
            float4 a = *(const float4*)xp;
            float4 b = *(const float4*)(xp + 4);
            uint4 hi, lo;
            split2(a.x, a.y, hi.x, lo.x);
            split2(a.z, a.w, hi.y, lo.y);
            split2(b.x, b.y, hi.z, lo.z);
            split2(b.z, b.w, hi.w, lo.w);
            *(uint4*)&Xh[r*WP + c8] = hi;
            *(uint4*)&Xl[r*WP + c8] = lo;
        }
        #pragma unroll
        for (int i = 0; i < 6; i++) {
            int f = t + 256 * i;               // 0..1535
            int r = f >> 3, c8 = (f & 7) * 8;
            *(uint4*)&Wh[r*WP + c8] = *(const uint4*)&g_wh[(size_t)r * E_ + k0 + c8];
            *(uint4*)&Wl[r*WP + c8] = *(const uint4*)&g_wl[(size_t)r * E_ + k0 + c8];
        }
        __syncthreads();

        #pragma unroll
        for (int kk = 0; kk < 4; kk++) {
            int kb = kk * 16 + kq;
            uint32_t Ah[4], Al[4];
            Ah[0] = *(const uint32_t*)&Xh[(r0  )*WP + kb  ];
            Ah[1] = *(const uint32_t*)&Xh[(r0+8)*WP + kb  ];
            Ah[2] = *(const uint32_t*)&Xh[(r0  )*WP + kb+8];
            Ah[3] = *(const uint32_t*)&Xh[(r0+8)*WP + kb+8];
            Al[0] = *(const uint32_t*)&Xl[(r0  )*WP + kb  ];
            Al[1] = *(const uint32_t*)&Xl[(r0+8)*WP + kb  ];
            Al[2] = *(const uint32_t*)&Xl[(r0  )*WP + kb+8];
            Al[3] = *(const uint32_t*)&Xl[(r0+8)*WP + kb+8];
            uint32_t Bh[12][2], Bl[12][2];
            #pragma unroll
            for (int p = 0; p < 6; p++) {
                int rowbase = nhalf*96 + 16*p + ksrow;
                ldsm4(Bh[2*p][0], Bh[2*p][1], Bh[2*p+1][0], Bh[2*p+1][1],
                      &Wh[rowbase*WP + kk*16 + ksk]);
                ldsm4(Bl[2*p][0], Bl[2*p][1], Bl[2*p+1][0], Bl[2*p+1][1],
                      &Wl[rowbase*WP + kk*16 + ksk]);
            }
            #pragma unroll
            for (int j = 0; j < 12; j++) mma_bf16(acc[j], Ah, Bh[j]);
            #pragma unroll
            for (int j = 0; j < 12; j++) mma_bf16(acc[j], Ah, Bl[j]);
            #pragma unroll
            for (int j = 0; j < 12; j++) mma_bf16(acc[j], Al, Bh[j]);
        }
    }

    const float* bs[3] = {bq, bk, bv};
    __nv_bfloat16* oh[3] = {g_qh, g_kh, g_vh};
    __nv_bfloat16* ol[3] = {g_ql, g_kl, g_vl};
    #pragma unroll
    for (int j = 0; j < 12; j++) {
        int gn = nhalf*12 + j;
        int ct = gn * 8 + kq;
        int mat = ct >> 6, cl = ct & 63;
        float sc = (mat == 0) ? 0.125f : 1.0f;
        float b0 = bs[mat][cl], b1 = bs[mat][cl+1];
        size_t row = (size_t)(m0 + r0);
        uint32_t h0, l0, h1, l1;
        split2((acc[j][0] + b0) * sc, (acc[j][1] + b1) * sc, h0, l0);
        split2((acc[j][2] + b0) * sc, (acc[j][3] + b1) * sc, h1, l1);
        *(uint32_t*)&oh[mat][ row      * H_ + cl] = h0;
        *(uint32_t*)&ol[mat][ row      * H_ + cl] = l0;
        *(uint32_t*)&oh[mat][(row + 8) * H_ + cl] = h1;
        *(uint32_t*)&ol[mat][(row + 8) * H_ + cl] = l1;
    }
}

// ---------------------------------------------------------------------------
// fa: grid (16, 8) = 128 CTAs, single wave. CTA x processes q-tiles 31-x
// then x (33 kv-tiles total per CTA -> perfect balance). 2 warp-groups split
// kt per q-tile; merge via smem.
// ---------------------------------------------------------------------------
__global__ __launch_bounds__(256) void fa_mma(float* __restrict__ Y)
{
    extern __shared__ __align__(16) __nv_bfloat16 fsm[];
    __nv_bfloat16* Qh = fsm;                       // [64][WP]
    __nv_bfloat16* Ql = fsm + 4608;

    const int b    = blockIdx.y;
    const int bx   = blockIdx.x;                   // 0..15
    const int t    = threadIdx.x;
    const int w    = t >> 5;
    const int lane = t & 31;
    const int rl   = lane >> 2;
    const int cq   = (lane & 3) * 2;
    const int g    = w >> 2;                       // warp group 0/1
    const int qrow = (w & 3) * 16 + rl;
    const int gt   = t & 127;
    const int ksrow = (lane & 7) + 8 * ((lane >> 4) & 1);
    const int ksk   = 8 * ((lane >> 3) & 1);
    const int vsrow = (lane & 7) + 8 * ((lane >> 3) & 1);
    const int vsh   = 8 * ((lane >> 4) & 1);

    __nv_bfloat16* Kh = fsm + 9216 + g * 18432;
    __nv_bfloat16* Kl = Kh + 4608;
    __nv_bfloat16* Vh = Kh + 9216;
    __nv_bfloat16* Vl = Kh + 13824;

    const size_t kvbase = (size_t)b * S_;
    float* mbuf = (float*)((char*)fsm + 55296);    // aliases group-1 KV; guarded by pass-end sync

    #pragma unroll 1
    for (int pass = 0; pass < 2; pass++) {
        const int qt = pass ? bx : 31 - bx;        // heavy tile first
        const size_t qbase = (size_t)(b * S_ + qt * 64);

        // Q tile (already scaled, pre-split)
        #pragma unroll
        for (int i = 0; i < 2; i++) {
            int f = t + 256 * i;                 // 0..511
            int r = f >> 3, c8 = (f & 7) * 8;
            *(uint4*)&Qh[r*WP + c8] = *(const uint4*)&g_qh[(qbase + r) * H_ + c8];
            *(uint4*)&Ql[r*WP + c8] = *(const uint4*)&g_ql[(qbase + r) * H_ + c8];
        }
        __syncthreads();

        uint32_t QAh[4][4], QAl[4][4];
        #pragma unroll
        for (int kk = 0; kk < 4; kk++) {
            int kb = kk * 16 + cq;
            QAh[kk][0] = *(const uint32_t*)&Qh[(qrow  )*WP + kb  ];
            QAh[kk][1] = *(const uint32_t*)&Qh[(qrow+8)*WP + kb  ];
            QAh[kk][2] = *(const uint32_t*)&Qh[(qrow  )*WP + kb+8];
            QAh[kk][3] = *(const uint32_t*)&Qh[(qrow+8)*WP + kb+8];
            QAl[kk][0] = *(const uint32_t*)&Ql[(qrow  )*WP + kb  ];
            QAl[kk][1] = *(const uint32_t*)&Ql[(qrow+8)*WP + kb  ];
            QAl[kk][2] = *(const uint32_t*)&Ql[(qrow  )*WP + kb+8];
            QAl[kk][3] = *(const uint32_t*)&Ql[(qrow+8)*WP + kb+8];
        }

        float o[8][4];
        #pragma unroll
        for (int j = 0; j < 8; j++)
            #pragma unroll
            for (int i = 0; i < 4; i++) o[j][i] = 0.f;
        float mrow[2] = {-1e30f, -1e30f};
        float lrow[2] = {0.f, 0.f};

        for (int kt = g; kt <= qt; kt += 2) {
            asm volatile("bar.sync %0, 128;" :: "r"(1 + g) : "memory");
            #pragma unroll
            for (int i = 0; i < 4; i++) {
                int f = gt + 128 * i;            // 0..511
                int r = f >> 3, c8 = (f & 7) * 8;
                size_t gi = (kvbase + kt * 64 + r) * H_ + c8;
                *(uint4*)&Kh[r*WP + c8] = *(const uint4*)&g_kh[gi];
                *(uint4*)&Kl[r*WP + c8] = *(const uint4*)&g_kl[gi];
                *(uint4*)&Vh[r*WP + c8] = *(const uint4*)&g_vh[gi];
                *(uint4*)&Vl[r*WP + c8] = *(const uint4*)&g_vl[gi];
            }
            asm volatile("bar.sync %0, 128;" :: "r"(1 + g) : "memory");

            // ---- S = Qs @ K^T ----
            float s[8][4];
            #pragma unroll
            for (int j = 0; j < 8; j++)
                #pragma unroll
                for (int i = 0; i < 4; i++) s[j][i] = 0.f;

            #pragma unroll
            for (int kk = 0; kk < 4; kk++) {
                uint32_t Bh[8][2], Bl[8][2];
                #pragma unroll
                for (int p = 0; p < 4; p++) {
                    ldsm4(Bh[2*p][0], Bh[2*p][1], Bh[2*p+1][0], Bh[2*p+1][1],
                          &Kh[(16*p + ksrow)*WP + kk*16 + ksk]);
                    ldsm4(Bl[2*p][0], Bl[2*p][1], Bl[2*p+1][0], Bl[2*p+1][1],
                          &Kl[(16*p + ksrow)*WP + kk*16 + ksk]);
                }
                #pragma unroll
                for (int j = 0; j < 8; j++) mma_bf16(s[j], QAh[kk], Bh[j]);
                #pragma unroll
                for (int j = 0; j < 8; j++) mma_bf16(s[j], QAh[kk], Bl[j]);
                #pragma unroll
                for (int j = 0; j < 8; j++) mma_bf16(s[j], QAl[kk], Bh[j]);
            }

            if (kt == qt) {
                #pragma unroll
                for (int j = 0; j < 8; j++) {
                    int c0 = j * 8 + cq;
                    if (c0     > qrow)     s[j][0] = -1e30f;
                    if (c0 + 1 > qrow)     s[j][1] = -1e30f;
                    if (c0     > qrow + 8) s[j][2] = -1e30f;
                    if (c0 + 1 > qrow + 8) s[j][3] = -1e30f;
                }
            }

            // ---- online softmax ----
            float mx0 = -1e30f, mx1 = -1e30f;
            #pragma unroll
            for (int j = 0; j < 8; j++) {
                mx0 = fmaxf(mx0, fmaxf(s[j][0], s[j][1]));
                mx1 = fmaxf(mx1, fmaxf(s[j][2], s[j][3]));
            }
            mx0 = fmaxf(mx0, __shfl_xor_sync(0xffffffffu, mx0, 1));
            mx0 = fmaxf(mx0, __shfl_xor_sync(0xffffffffu, mx0, 2));
            mx1 = fmaxf(mx1, __shfl_xor_sync(0xffffffffu, mx1, 1));
            mx1 = fmaxf(mx1, __shfl_xor_sync(0xffffffffu, mx1, 2));

            float mn0 = fmaxf(mrow[0], mx0), mn1 = fmaxf(mrow[1], mx1);
            float corr0 = __expf(mrow[0] - mn0), corr1 = __expf(mrow[1] - mn1);
            mrow[0] = mn0; mrow[1] = mn1;

            float sum0 = 0.f, sum1 = 0.f;
            #pragma unroll
            for (int j = 0; j < 8; j++) {
                s[j][0] = __expf(s[j][0] - mn0);
                s[j][1] = __expf(s[j][1] - mn0);
                s[j][2] = __expf(s[j][2] - mn1);
                s[j][3] = __expf(s[j][3] - mn1);
                sum0 += s[j][0] + s[j][1];
                sum1 += s[j][2] + s[j][3];
            }
            sum0 += __shfl_xor_sync(0xffffffffu, sum0, 1);
            sum0 += __shfl_xor_sync(0xffffffffu, sum0, 2);
            sum1 += __shfl_xor_sync(0xffffffffu, sum1, 1);
            sum1 += __shfl_xor_sync(0xffffffffu, sum1, 2);
            lrow[0] = lrow[0] * corr0 + sum0;
            lrow[1] = lrow[1] * corr1 + sum1;

            #pragma unroll
            for (int j = 0; j < 8; j++) {
                o[j][0] *= corr0; o[j][1] *= corr0;
                o[j][2] *= corr1; o[j][3] *= corr1;
            }

            // ---- P frags (hi/lo) in regs ----
            uint32_t Ph[4][4], Pl[4][4];
            #pragma unroll
            for (int kk = 0; kk < 4; kk++) {
                #pragma unroll
                for (int half = 0; half < 2; half++) {
                    int jj = 2*kk + half;
                    split2(s[jj][0], s[jj][1], Ph[kk][half*2+0], Pl[kk][half*2+0]);
                    split2(s[jj][2], s[jj][3], Ph[kk][half*2+1], Pl[kk][half*2+1]);
                }
            }

            // ---- O += P @ V ----
            #pragma unroll
            for (int kk = 0; kk < 4; kk++) {
                uint32_t Bh[8][2], Bl[8][2];
                #pragma unroll
                for (int p = 0; p < 4; p++) {
                    ldsm4t(Bh[2*p][0], Bh[2*p][1], Bh[2*p+1][0], Bh[2*p+1][1],
                           &Vh[(kk*16 + vsrow)*WP + 16*p + vsh]);
                    ldsm4t(Bl[2*p][0], Bl[2*p][1], Bl[2*p+1][0], Bl[2*p+1][1],
                           &Vl[(kk*16 + vsrow)*WP + 16*p + vsh]);
                }
                #pragma unroll
                for (int jh = 0; jh < 8; jh++) mma_bf16(o[jh], Ph[kk], Bh[jh]);
                #pragma unroll
                for (int jh = 0; jh < 8; jh++) mma_bf16(o[jh], Ph[kk], Bl[jh]);
                #pragma unroll
                for (int jh = 0; jh < 8; jh++) mma_bf16(o[jh], Pl[kk], Bh[jh]);
            }
        }

        // ---- merge the two groups' partial states ----
        __syncthreads();   // both groups done with KV smem (group 1's aliases mbuf)
        if (g == 1) {
            float* p = mbuf + gt * 37;
            p[0] = mrow[0]; p[1] = mrow[1]; p[2] = lrow[0]; p[3] = lrow[1];
            #pragma unroll
            for (int j = 0; j < 8; j++)
                #pragma unroll
                for (int i = 0; i < 4; i++) p[4 + j*4 + i] = o[j][i];
        }
        __syncthreads();
        if (g == 0) {
            const float* p = mbuf + gt * 37;
            float m1a = p[0], m1b = p[1], l1a = p[2], l1b = p[3];
            float mA = fmaxf(mrow[0], m1a), mB = fmaxf(mrow[1], m1b);
            float w0a = __expf(mrow[0] - mA), w1a = __expf(m1a - mA);
            float w0b = __expf(mrow[1] - mB), w1b = __expf(m1b - mB);
            float invA = 1.0f / (lrow[0] * w0a + l1a * w1a);
            float invB = 1.0f / (lrow[1] * w0b + l1b * w1b);
            float* Yb = Y + qbase * H_;
            #pragma unroll
            for (int j = 0; j < 8; j++) {
                int col = j * 8 + cq;
                float oa0 = (o[j][0] * w0a + p[4 + j*4 + 0] * w1a) * invA;
                float oa1 = (o[j][1] * w0a + p[4 + j*4 + 1] * w1a) * invA;
                float ob0 = (o[j][2] * w0b + p[4 + j*4 + 2] * w1b) * invB;
                float ob1 = (o[j][3] * w0b + p[4 + j*4 + 3] * w1b) * invB;
                *(float2*)(Yb + (size_t)(qrow    ) * H_ + col) = make_float2(oa0, oa1);
                *(float2*)(Yb + (size_t)(qrow + 8) * H_ + col) = make_float2(ob0, ob1);
            }
        }
        __syncthreads();   // mbuf consumed; Q smem free for next pass
    }
}

// ---------------------------------------------------------------------------
extern "C" void kernel_launch(void* const* d_in, const int* in_sizes, int n_in,
                              void* d_out, int out_size)
{
    const float* x  = (const float*)d_in[0];
    const float* wq = (const float*)d_in[1];
    const float* bq = (const float*)d_in[2];
    const float* wk = (const float*)d_in[3];
    const float* bk = (const float*)d_in[4];
    const float* wv = (const float*)d_in[5];
    const float* bv = (const float*)d_in[6];
    float* y = (float*)d_out;

    convert_w<<<dim3(16, 3), 256>>>(wq, wk, wv);

    const int qsh = (4608*2 + 13824*2) * (int)sizeof(__nv_bfloat16);  // 73728
    cudaFuncSetAttribute(qkv_mma, cudaFuncAttributeMaxDynamicSharedMemorySize, qsh);
    qkv_mma<<<M_/64, 256, qsh>>>(x, bq, bk, bv);

    const int fsh = (9216 + 2*18432) * (int)sizeof(__nv_bfloat16);    // 92160
    cudaFuncSetAttribute(fa_mma, cudaFuncAttributeMaxDynamicSharedMemorySize, fsh);
    fa_mma<<<dim3(16, B_), 256, fsh>>>(y);
}